// round 16
// baseline (speedup 1.0000x reference)
#include <cuda_runtime.h>
#include <cstddef>

#define GH    128
#define GW    128
#define GV    16384
#define GB    16
#define GFIN  32
#define GK    5
#define GFOUT 32
#define NROW  512          // GB*GFIN independent images
#define F4V   4096         // float4s per image
#define HROW  256          // rows per half-chunk
#define HB    8            // batches per half-chunk

// T1..T4 storage: g_terms[k-1][row][V]  (T0 is x itself).
// Device-side references ONLY (host shadow address is poison).
__device__ float g_terms[4][NROW][GV];

typedef unsigned long long ull;

__device__ __forceinline__ ull pack2(float x) {
    ull r;
    asm("mov.b64 %0, {%1, %1};" : "=l"(r) : "f"(x));
    return r;
}
__device__ __forceinline__ void ffma2(ull& d, ull a, ull b) {
    asm("fma.rn.f32x2 %0, %1, %2, %0;" : "+l"(d) : "l"(a), "l"(b));
}
__device__ __forceinline__ float ulo(ull a) { return __uint_as_float((unsigned)(a & 0xffffffffull)); }
__device__ __forceinline__ float uhi(ull a) { return __uint_as_float((unsigned)(a >> 32)); }

// ---------------------------------------------------------------------------
// Flat Chebyshev pass on a 256-image chunk, native [row][128x128] layout.
//   (scaled L)y = e*sum4(y) + (-deg*e-1)*y,   e = lap_vals[0] = -2/lmax
//   k==1: T1 = L*x ; k>=2: Tk = 2*L*T_{k-1} - T_{k-2}
// Identical math to the measured 15.8us/pass kernel; row0 selects the chunk
// so the chunk working set stays L2-resident across passes + contraction.
// ---------------------------------------------------------------------------
__global__ void __launch_bounds__(256) stencil_pass(
        const float* __restrict__ x, const float* __restrict__ lap_vals,
        int k, int row0) {
    const float* __restrict__ Y;
    const float* __restrict__ P;
    float*       __restrict__ O;
    if      (k == 1) { Y = x;                  P = x;                  O = &g_terms[0][0][0]; }
    else if (k == 2) { Y = &g_terms[0][0][0];  P = x;                  O = &g_terms[1][0][0]; }
    else if (k == 3) { Y = &g_terms[1][0][0];  P = &g_terms[0][0][0];  O = &g_terms[2][0][0]; }
    else             { Y = &g_terms[2][0][0];  P = &g_terms[1][0][0];  O = &g_terms[3][0][0]; }
    const size_t roff = (size_t)row0 * GV;
    Y += roff; P += roff; O += roff;

    const float e = lap_vals[0];
    const int gid = blockIdx.x * 256 + threadIdx.x;     // f4 index within chunk
    const int p   = gid & (F4V - 1);                    // f4 within image
    const int i   = p >> 5;                             // row 0..127
    const int j4  = p & 31;                             // f4 col 0..31

    const float4* __restrict__ Y4 = (const float4*)Y;
    const float4  zero4 = make_float4(0.f, 0.f, 0.f, 0.f);

    float4 c  = Y4[gid];
    float4 up = (i > 0)       ? Y4[gid - 32] : zero4;
    float4 dn = (i < GH - 1)  ? Y4[gid + 32] : zero4;
    float lft = (j4 > 0)      ? Y[(size_t)gid * 4 - 1] : 0.f;
    float rgt = (j4 < 31)     ? Y[(size_t)gid * 4 + 4] : 0.f;

    const float degi = (float)((i > 0) + (i < GH - 1));
    float dx = degi + (float)((j4 > 0) + 1);
    float dy = degi + 2.f;
    float dz = degi + 2.f;
    float dw = degi + (float)(1 + (j4 < 31));

    float4 s;
    s.x = lft + c.y + up.x + dn.x;
    s.y = c.x + c.z + up.y + dn.y;
    s.z = c.y + c.w + up.z + dn.z;
    s.w = c.z + rgt + up.w + dn.w;

    float4 L;
    L.x = e * s.x + (-dx * e - 1.f) * c.x;
    L.y = e * s.y + (-dy * e - 1.f) * c.y;
    L.z = e * s.z + (-dz * e - 1.f) * c.z;
    L.w = e * s.w + (-dw * e - 1.f) * c.w;

    float4 r;
    if (k == 1) {
        r = L;
    } else {
        float4 pv = ((const float4*)P)[gid];
        r.x = 2.f * L.x - pv.x;
        r.y = 2.f * L.y - pv.y;
        r.z = 2.f * L.z - pv.z;
        r.w = 2.f * L.w - pv.w;
    }
    ((float4*)O)[gid] = r;
}

// ---------------------------------------------------------------------------
// Contraction: out[b][o][v] = sum_{k,f} T_k[b*32+f][v] * W[f][k][o] + bias[o]
// Thread tile: 4 v (float4) x 16 o (one o-half). Per f iteration all FIVE
// k-term loads in flight (MLP=5), then 5 x (4 LDS.128 + 32 FFMA2).
// b0 selects the batch chunk (terms are L2-hot right after its stencils).
// ---------------------------------------------------------------------------
__global__ void __launch_bounds__(256, 2) contract_kernel(
        const float* __restrict__ x, const float* __restrict__ weight,
        const float* __restrict__ bias, float* __restrict__ out, int b0) {
    __shared__ __align__(16) float2 Wsf[GK * GFIN * 16];   // [k][f][q]: pair (2q, 2q+1)
    __shared__ float bsm[GFOUT];

    const int tid = threadIdx.x;
    for (int idx = tid; idx < GK * GFIN * 16; idx += 256) {
        int q = idx & 15, f = (idx >> 4) & 31, k = idx >> 9;
        const float* wsrc = weight + ((size_t)f * GK + k) * GFOUT + q * 2;
        Wsf[idx] = make_float2(wsrc[0], wsrc[1]);
    }
    if (tid < GFOUT) bsm[tid] = bias[tid];
    __syncthreads();

    const int b     = b0 + (blockIdx.x >> 5);
    const int v4    = ((blockIdx.x & 31) << 7) + (tid & 127);   // f4 index in image
    const int ohalf = tid >> 7;                                  // 0 or 1

    const int rowoff = (b * GFIN) << 12;       // float4 offset of row (b,f=0)
    const float4* __restrict__ t0 = (const float4*)x                 + rowoff + v4;
    const float4* __restrict__ t1 = (const float4*)&g_terms[0][0][0] + rowoff + v4;
    const float4* __restrict__ t2 = (const float4*)&g_terms[1][0][0] + rowoff + v4;
    const float4* __restrict__ t3 = (const float4*)&g_terms[2][0][0] + rowoff + v4;
    const float4* __restrict__ t4 = (const float4*)&g_terms[3][0][0] + rowoff + v4;

    const ull* __restrict__ WsU = (const ull*)Wsf;

    ull acc[4][8];
#pragma unroll
    for (int vi = 0; vi < 4; vi++)
#pragma unroll
        for (int q = 0; q < 8; q++) acc[vi][q] = 0ull;

    // one k-term contribution: 4 LDS.128 + 32 FFMA2
    auto dok = [&](float4 c, const ulonglong2* wp) {
        ulonglong2 w01 = wp[0], w23 = wp[1], w45 = wp[2], w67 = wp[3];
        ull pk[4];
        pk[0] = pack2(c.x); pk[1] = pack2(c.y); pk[2] = pack2(c.z); pk[3] = pack2(c.w);
#pragma unroll
        for (int vi = 0; vi < 4; vi++) {
            ffma2(acc[vi][0], pk[vi], w01.x);
            ffma2(acc[vi][1], pk[vi], w01.y);
            ffma2(acc[vi][2], pk[vi], w23.x);
            ffma2(acc[vi][3], pk[vi], w23.y);
            ffma2(acc[vi][4], pk[vi], w45.x);
            ffma2(acc[vi][5], pk[vi], w45.y);
            ffma2(acc[vi][6], pk[vi], w67.x);
            ffma2(acc[vi][7], pk[vi], w67.y);
        }
    };

#pragma unroll 1
    for (int f = 0; f < GFIN; f++) {
        const int fo = f << 12;
        // all five term loads in flight before any consumption (MLP = 5)
        float4 c0 = t0[fo];
        float4 c1 = t1[fo];
        float4 c2 = t2[fo];
        float4 c3 = t3[fo];
        float4 c4 = t4[fo];

        const ull* wf = WsU + f * 16 + ohalf * 8;
        dok(c0, (const ulonglong2*)(wf));
        dok(c1, (const ulonglong2*)(wf + 512));
        dok(c2, (const ulonglong2*)(wf + 1024));
        dok(c3, (const ulonglong2*)(wf + 1536));
        dok(c4, (const ulonglong2*)(wf + 2048));
    }

    // epilogue: o = ohalf*16 + 2q (+1); float4 stores along v
    float4* __restrict__ out4 = (float4*)out;
#pragma unroll
    for (int q = 0; q < 8; q++) {
        int o = ohalf * 16 + q * 2;
        float blo = bsm[o], bhi = bsm[o + 1];
        float4 rlo = make_float4(ulo(acc[0][q]) + blo, ulo(acc[1][q]) + blo,
                                 ulo(acc[2][q]) + blo, ulo(acc[3][q]) + blo);
        float4 rhi = make_float4(uhi(acc[0][q]) + bhi, uhi(acc[1][q]) + bhi,
                                 uhi(acc[2][q]) + bhi, uhi(acc[3][q]) + bhi);
        out4[((b * GFOUT + o)     << 12) + v4] = rlo;
        out4[((b * GFOUT + o + 1) << 12) + v4] = rhi;
    }
}

// ---------------------------------------------------------------------------
extern "C" void kernel_launch(void* const* d_in, const int* in_sizes, int n_in,
                              void* d_out, int out_size) {
    const float* x        = (const float*)d_in[0];
    const float* weight   = (const float*)d_in[1];
    const float* bias     = (const float*)d_in[2];
    const float* lap_vals = (const float*)d_in[3];
    // d_in[4]=rows, d_in[5]=cols unused: grid structure is implicit.
    float* out = (float*)d_out;

    const int sblocks = HROW * F4V / 256;     // 4096 blocks per half-chunk
    const int cblocks = HB * 32;              // 256 blocks per half-chunk

    // Half-batch chunks: each chunk's x + T1..T4 + out slice (~100 MB) stays
    // L2-resident across its 4 stencil passes + contraction.
    for (int h = 0; h < 2; h++) {
        const int row0 = h * HROW;
        const int b0   = h * HB;
        stencil_pass<<<sblocks, 256>>>(x, lap_vals, 1, row0);
        stencil_pass<<<sblocks, 256>>>(x, lap_vals, 2, row0);
        stencil_pass<<<sblocks, 256>>>(x, lap_vals, 3, row0);
        stencil_pass<<<sblocks, 256>>>(x, lap_vals, 4, row0);
        contract_kernel<<<cblocks, 256>>>(x, weight, bias, out, b0);
    }
}

// round 17
// speedup vs baseline: 1.0393x; 1.0393x over previous
#include <cuda_runtime.h>
#include <cstddef>

#define GH    128
#define GW    128
#define GV    16384
#define GB    16
#define GFIN  32
#define GK    5
#define GFOUT 32
#define NROW  512          // GB*GFIN independent images
#define F4V   4096         // float4s per image

// T1..T4 storage: g_terms[k-1][row][V]  (T0 is x itself).
// Device-side references ONLY (host shadow address is poison).
__device__ float g_terms[4][NROW][GV];

typedef unsigned long long ull;

__device__ __forceinline__ ull pack2(float x) {
    ull r;
    asm("mov.b64 %0, {%1, %1};" : "=l"(r) : "f"(x));
    return r;
}
__device__ __forceinline__ void ffma2(ull& d, ull a, ull b) {
    asm("fma.rn.f32x2 %0, %1, %2, %0;" : "+l"(d) : "l"(a), "l"(b));
}
__device__ __forceinline__ float ulo(ull a) { return __uint_as_float((unsigned)(a & 0xffffffffull)); }
__device__ __forceinline__ float uhi(ull a) { return __uint_as_float((unsigned)(a >> 32)); }

// L of a float4 given neighbors + position (scaled Laplacian):
//   L = e*(lft,c-internal,rgt + up + dn) + (-deg*e-1)*c
__device__ __forceinline__ float4 lap4(float4 c, float4 up, float4 dn,
                                       float lft, float rgt,
                                       int gi, int j4, float e) {
    const float degi = (float)((gi > 0) + (gi < GH - 1));
    float dx = degi + (float)((j4 > 0) + 1);
    float dy = degi + 2.f;
    float dz = degi + 2.f;
    float dw = degi + (float)(1 + (j4 < 31));
    float4 s;
    s.x = lft + c.y + up.x + dn.x;
    s.y = c.x + c.z + up.y + dn.y;
    s.z = c.y + c.w + up.z + dn.z;
    s.w = c.z + rgt + up.w + dn.w;
    float4 L;
    L.x = e * s.x + (-dx * e - 1.f) * c.x;
    L.y = e * s.y + (-dy * e - 1.f) * c.y;
    L.z = e * s.z + (-dz * e - 1.f) * c.z;
    L.w = e * s.w + (-dw * e - 1.f) * c.w;
    return L;
}

// ---------------------------------------------------------------------------
// Fused double Chebyshev step on an 8-row full-width strip (halo 2 rows).
//   first=1 : Z1 = L*x          ; Z2 = 2*L*Z1 - x    -> T1, T2
//   first=0 : Z1 = 2*L*T2 - T1  ; Z2 = 2*L*Z1 - T2   -> T3, T4
// Full-width rows => no horizontal halo; j+-1 always in smem.
// Out-of-grid rows are zero in smem (zero-neighbor boundary semantics).
// Block 256 = 8 row-workers x 32 f4-cols; all index math is shifts/masks.
// ---------------------------------------------------------------------------
__global__ void __launch_bounds__(256) fused2_pass(
        const float* __restrict__ x, const float* __restrict__ lap_vals,
        int first) {
    const float* __restrict__ Y  = first ? x : &g_terms[1][0][0];
    const float* __restrict__ P  = first ? x : &g_terms[0][0][0];
    float*       __restrict__ O1 = first ? &g_terms[0][0][0] : &g_terms[2][0][0];
    float*       __restrict__ O2 = first ? &g_terms[1][0][0] : &g_terms[3][0][0];

    __shared__ float sy[12][128];
    __shared__ float sp[12][128];
    __shared__ float sz[12][128];

    const int tid = threadIdx.x;
    const int w   = tid >> 5;        // row worker 0..7
    const int j4  = tid & 31;        // f4 column
    const int r   = blockIdx.y;      // image row (b*32+f)
    const int i0  = blockIdx.x << 3; // strip origin (global row)

    const size_t ibase = (size_t)r * GV;
    const float e = lap_vals[0];
    const float4 z4 = make_float4(0.f, 0.f, 0.f, 0.f);

    // load 12 rows (i0-2 .. i0+9), OOB rows -> 0
    for (int lr = w; lr < 12; lr += 8) {
        int gi = i0 - 2 + lr;
        float4 vy = z4, vp = z4;
        if ((unsigned)gi < GH) {
            vy = ((const float4*)(Y + ibase + gi * GW))[j4];
            if (!first) vp = ((const float4*)(P + ibase + gi * GW))[j4];
        }
        *(float4*)&sy[lr][j4 * 4] = vy;
        if (!first) *(float4*)&sp[lr][j4 * 4] = vp;
    }
    __syncthreads();

    // Z1 on local rows 1..10 (global i0-1 .. i0+8); OOB rows -> 0
    for (int lr = 1 + w; lr <= 10; lr += 8) {
        int gi = i0 - 2 + lr;
        float4 res = z4;
        if ((unsigned)gi < GH) {
            float4 c  = *(float4*)&sy[lr][j4 * 4];
            float4 up = *(float4*)&sy[lr - 1][j4 * 4];
            float4 dn = *(float4*)&sy[lr + 1][j4 * 4];
            float lft = (j4 > 0)  ? sy[lr][j4 * 4 - 1] : 0.f;
            float rgt = (j4 < 31) ? sy[lr][j4 * 4 + 4] : 0.f;
            float4 L = lap4(c, up, dn, lft, rgt, gi, j4, e);
            if (first) {
                res = L;
            } else {
                float4 pv = *(float4*)&sp[lr][j4 * 4];
                res.x = 2.f * L.x - pv.x;
                res.y = 2.f * L.y - pv.y;
                res.z = 2.f * L.z - pv.z;
                res.w = 2.f * L.w - pv.w;
            }
        }
        *(float4*)&sz[lr][j4 * 4] = res;
    }
    __syncthreads();

    // Z2 on center rows (local 2..9, global i0..i0+7); store Z1 + Z2
    {
        int lr = 2 + w;
        int gi = i0 - 2 + lr;            // always in [0,127]
        float4 c  = *(float4*)&sz[lr][j4 * 4];
        float4 up = *(float4*)&sz[lr - 1][j4 * 4];
        float4 dn = *(float4*)&sz[lr + 1][j4 * 4];
        float lft = (j4 > 0)  ? sz[lr][j4 * 4 - 1] : 0.f;
        float rgt = (j4 < 31) ? sz[lr][j4 * 4 + 4] : 0.f;
        float4 L = lap4(c, up, dn, lft, rgt, gi, j4, e);
        float4 yv = *(float4*)&sy[lr][j4 * 4];
        float4 z2;
        z2.x = 2.f * L.x - yv.x;
        z2.y = 2.f * L.y - yv.y;
        z2.z = 2.f * L.z - yv.z;
        z2.w = 2.f * L.w - yv.w;
        ((float4*)(O1 + ibase + gi * GW))[j4] = c;    // Z1 (center)
        ((float4*)(O2 + ibase + gi * GW))[j4] = z2;   // Z2
    }
}

// ---------------------------------------------------------------------------
// Contraction: out[b][o][v] = sum_{k,f} T_k[b*32+f][v] * W[f][k][o] + bias[o]
// Thread tile: 4 v (float4) x 16 o (one o-half). Per f iteration all FIVE
// k-term loads in flight (MLP=5), then 5 x (4 LDS.128 + 32 FFMA2).
// (byte-identical to the R15 kernel measured at ~68us)
// ---------------------------------------------------------------------------
__global__ void __launch_bounds__(256, 2) contract_kernel(
        const float* __restrict__ x, const float* __restrict__ weight,
        const float* __restrict__ bias, float* __restrict__ out) {
    __shared__ __align__(16) float2 Wsf[GK * GFIN * 16];   // [k][f][q]: pair (2q, 2q+1)
    __shared__ float bsm[GFOUT];

    const int tid = threadIdx.x;
    for (int idx = tid; idx < GK * GFIN * 16; idx += 256) {
        int q = idx & 15, f = (idx >> 4) & 31, k = idx >> 9;
        const float* wsrc = weight + ((size_t)f * GK + k) * GFOUT + q * 2;
        Wsf[idx] = make_float2(wsrc[0], wsrc[1]);
    }
    if (tid < GFOUT) bsm[tid] = bias[tid];
    __syncthreads();

    const int b     = blockIdx.x >> 5;
    const int v4    = ((blockIdx.x & 31) << 7) + (tid & 127);   // f4 index in image
    const int ohalf = tid >> 7;                                  // 0 or 1

    const int rowoff = (b * GFIN) << 12;       // float4 offset of row (b,f=0)
    const float4* __restrict__ t0 = (const float4*)x                 + rowoff + v4;
    const float4* __restrict__ t1 = (const float4*)&g_terms[0][0][0] + rowoff + v4;
    const float4* __restrict__ t2 = (const float4*)&g_terms[1][0][0] + rowoff + v4;
    const float4* __restrict__ t3 = (const float4*)&g_terms[2][0][0] + rowoff + v4;
    const float4* __restrict__ t4 = (const float4*)&g_terms[3][0][0] + rowoff + v4;

    const ull* __restrict__ WsU = (const ull*)Wsf;

    ull acc[4][8];
#pragma unroll
    for (int vi = 0; vi < 4; vi++)
#pragma unroll
        for (int q = 0; q < 8; q++) acc[vi][q] = 0ull;

    // one k-term contribution: 4 LDS.128 + 32 FFMA2
    auto dok = [&](float4 c, const ulonglong2* wp) {
        ulonglong2 w01 = wp[0], w23 = wp[1], w45 = wp[2], w67 = wp[3];
        ull pk[4];
        pk[0] = pack2(c.x); pk[1] = pack2(c.y); pk[2] = pack2(c.z); pk[3] = pack2(c.w);
#pragma unroll
        for (int vi = 0; vi < 4; vi++) {
            ffma2(acc[vi][0], pk[vi], w01.x);
            ffma2(acc[vi][1], pk[vi], w01.y);
            ffma2(acc[vi][2], pk[vi], w23.x);
            ffma2(acc[vi][3], pk[vi], w23.y);
            ffma2(acc[vi][4], pk[vi], w45.x);
            ffma2(acc[vi][5], pk[vi], w45.y);
            ffma2(acc[vi][6], pk[vi], w67.x);
            ffma2(acc[vi][7], pk[vi], w67.y);
        }
    };

#pragma unroll 1
    for (int f = 0; f < GFIN; f++) {
        const int fo = f << 12;
        // all five term loads in flight before any consumption (MLP = 5)
        float4 c0 = t0[fo];
        float4 c1 = t1[fo];
        float4 c2 = t2[fo];
        float4 c3 = t3[fo];
        float4 c4 = t4[fo];

        const ull* wf = WsU + f * 16 + ohalf * 8;
        dok(c0, (const ulonglong2*)(wf));
        dok(c1, (const ulonglong2*)(wf + 512));
        dok(c2, (const ulonglong2*)(wf + 1024));
        dok(c3, (const ulonglong2*)(wf + 1536));
        dok(c4, (const ulonglong2*)(wf + 2048));
    }

    // epilogue: o = ohalf*16 + 2q (+1); float4 stores along v
    float4* __restrict__ out4 = (float4*)out;
#pragma unroll
    for (int q = 0; q < 8; q++) {
        int o = ohalf * 16 + q * 2;
        float blo = bsm[o], bhi = bsm[o + 1];
        float4 rlo = make_float4(ulo(acc[0][q]) + blo, ulo(acc[1][q]) + blo,
                                 ulo(acc[2][q]) + blo, ulo(acc[3][q]) + blo);
        float4 rhi = make_float4(uhi(acc[0][q]) + bhi, uhi(acc[1][q]) + bhi,
                                 uhi(acc[2][q]) + bhi, uhi(acc[3][q]) + bhi);
        out4[((b * GFOUT + o)     << 12) + v4] = rlo;
        out4[((b * GFOUT + o + 1) << 12) + v4] = rhi;
    }
}

// ---------------------------------------------------------------------------
extern "C" void kernel_launch(void* const* d_in, const int* in_sizes, int n_in,
                              void* d_out, int out_size) {
    const float* x        = (const float*)d_in[0];
    const float* weight   = (const float*)d_in[1];
    const float* bias     = (const float*)d_in[2];
    const float* lap_vals = (const float*)d_in[3];
    // d_in[4]=rows, d_in[5]=cols unused: grid structure is implicit.
    float* out = (float*)d_out;

    dim3 sgrid(16, NROW);            // 16 strips x 512 images
    fused2_pass<<<sgrid, 256>>>(x, lap_vals, 1);   // T1, T2
    fused2_pass<<<sgrid, 256>>>(x, lap_vals, 0);   // T3, T4

    contract_kernel<<<512, 256>>>(x, weight, bias, out);
}